// round 13
// baseline (speedup 1.0000x reference)
#include <cuda_runtime.h>

#define NGMAX 4096
#define DCOLS 128
__device__ float g_Z[NGMAX];                 // zero-init at load; reset by fin_kernel
__device__ float g_S[NGMAX * DCOLS];         // zero-init at load; reset by fin_kernel

__device__ __forceinline__ float warp_bcast_sum(float p) {
    p += __shfl_xor_sync(0xFFFFFFFFu, p, 16);
    p += __shfl_xor_sync(0xFFFFFFFFu, p, 8);
    p += __shfl_xor_sync(0xFFFFFFFFu, p, 4);
    p += __shfl_xor_sync(0xFFFFFFFFu, p, 2);
    p += __shfl_xor_sync(0xFFFFFFFFu, p, 1);
    return p;
}

// One warp per chunk of rows_per_warp contiguous rows.
// Lane k holds columns [4k, 4k+4) as a float4. 4-row software pipeline
// (R3-proven form, frozen). Accumulates into device scratch g_S / g_Z.
// All index math 32-bit (V*DCOLS = 128M < 2^31) to cut register pressure
// and reach 6 CTAs/SM.
__global__ void __launch_bounds__(256, 6)
agg_kernel(const float* __restrict__ H,
           const int*   __restrict__ batch,
           const float* __restrict__ w,
           const float* __restrict__ b,
           int V, int rows_per_warp) {
    int warp = (blockIdx.x * blockDim.x + threadIdx.x) >> 5;
    int lane = threadIdx.x & 31;

    int start = warp * rows_per_warp;
    if (start >= V) return;
    int end = start + rows_per_warp;
    if (end > V) end = V;

    float4 w4 = reinterpret_cast<const float4*>(w)[lane];
    float bias = b[0];

    // per-lane base pointer into H (element offset fits in 32-bit)
    const float4* __restrict__ Hp =
        reinterpret_cast<const float4*>(H) + (unsigned)start * (DCOLS / 4) + lane;

    float4 acc = make_float4(0.f, 0.f, 0.f, 0.f);
    float  zacc = 0.f;
    int    seg  = batch[start];

#define FLUSH()                                                         \
    do {                                                                \
        float* o = g_S + seg * DCOLS + lane * 4;                        \
        atomicAdd(o + 0, acc.x);                                        \
        atomicAdd(o + 1, acc.y);                                        \
        atomicAdd(o + 2, acc.z);                                        \
        atomicAdd(o + 3, acc.w);                                        \
        if (lane == 0) atomicAdd(&g_Z[seg], zacc);                      \
        acc = make_float4(0.f, 0.f, 0.f, 0.f);                          \
        zacc = 0.f;                                                     \
    } while (0)

#define ACCUM(s_, h_, l_)                                               \
    do {                                                                \
        if ((s_) != seg) { FLUSH(); seg = (s_); }                       \
        acc.x += (l_) * (h_).x;                                         \
        acc.y += (l_) * (h_).y;                                         \
        acc.z += (l_) * (h_).z;                                         \
        acc.w += (l_) * (h_).w;                                         \
        zacc  += (l_);                                                  \
    } while (0)

    int r = start;
    for (; r + 4 <= end; r += 4, Hp += 4 * (DCOLS / 4)) {
        // front-batched independent loads (MLP); streaming hint: H read once
        int4   bv = *reinterpret_cast<const int4*>(batch + r);
        float4 h0 = __ldcs(Hp + 0 * (DCOLS / 4));
        float4 h1 = __ldcs(Hp + 1 * (DCOLS / 4));
        float4 h2 = __ldcs(Hp + 2 * (DCOLS / 4));
        float4 h3 = __ldcs(Hp + 3 * (DCOLS / 4));

        float p0 = h0.x * w4.x + h0.y * w4.y + h0.z * w4.z + h0.w * w4.w;
        float p1 = h1.x * w4.x + h1.y * w4.y + h1.z * w4.z + h1.w * w4.w;
        float p2 = h2.x * w4.x + h2.y * w4.y + h2.z * w4.z + h2.w * w4.w;
        float p3 = h3.x * w4.x + h3.y * w4.y + h3.z * w4.z + h3.w * w4.w;

        // four independent butterfly chains — latencies overlap
        #pragma unroll
        for (int m = 16; m >= 1; m >>= 1) {
            p0 += __shfl_xor_sync(0xFFFFFFFFu, p0, m);
            p1 += __shfl_xor_sync(0xFFFFFFFFu, p1, m);
            p2 += __shfl_xor_sync(0xFFFFFFFFu, p2, m);
            p3 += __shfl_xor_sync(0xFFFFFFFFu, p3, m);
        }

        float l0 = __expf(p0 + bias);
        float l1 = __expf(p1 + bias);
        float l2 = __expf(p2 + bias);
        float l3 = __expf(p3 + bias);

        ACCUM(bv.x, h0, l0);
        ACCUM(bv.y, h1, l1);
        ACCUM(bv.z, h2, l2);
        ACCUM(bv.w, h3, l3);
    }

    // tail
    for (; r < end; ++r, Hp += (DCOLS / 4)) {
        int s = batch[r];
        float4 h = __ldcs(Hp);
        float p = h.x * w4.x + h.y * w4.y + h.z * w4.z + h.w * w4.w;
        p = warp_bcast_sum(p);
        float l = __expf(p + bias);
        ACCUM(s, h, l);
    }

    FLUSH();
#undef ACCUM
#undef FLUSH
}

// out[i] = S[i] / Z[i/128]; then reset scratch to zero for the next replay.
// All 32 threads of a warp read the same g_Z[g] (i>>5 constant per warp),
// so lane 0 can safely re-zero it after __syncwarp().
__global__ void fin_kernel(float4* __restrict__ out4, int n4) {
    int i = blockIdx.x * blockDim.x + threadIdx.x;
    if (i >= n4) return;
    int g = i >> 5;                 // (i*4)/128
    float z = g_Z[g];
    float4 v = reinterpret_cast<float4*>(g_S)[i];
    if (z > 0.f) {
        float inv = 1.0f / z;
        v.x *= inv; v.y *= inv; v.z *= inv; v.w *= inv;
    } else {
        v = make_float4(0.f, 0.f, 0.f, 0.f);
    }
    out4[i] = v;
    // reset scratch for next graph replay
    reinterpret_cast<float4*>(g_S)[i] = make_float4(0.f, 0.f, 0.f, 0.f);
    __syncwarp();
    if ((i & 31) == 0) g_Z[g] = 0.f;
}

extern "C" void kernel_launch(void* const* d_in, const int* in_sizes, int n_in,
                              void* d_out, int out_size) {
    const float* H     = (const float*)d_in[0];
    const int*   batch = (const int*)d_in[1];
    const float* w     = (const float*)d_in[2];
    const float* b     = (const float*)d_in[3];
    float*       out   = (float*)d_out;

    int V  = in_sizes[1];           // number of rows
    int n4 = out_size / 4;          // float4 count (= ng*32)

    {
        const int rows_per_warp = 64;
        long warps = ((long)V + rows_per_warp - 1) / rows_per_warp;
        int threads = 256;
        long blocks = (warps * 32 + threads - 1) / threads;
        agg_kernel<<<(int)blocks, threads>>>(H, batch, w, b, V, rows_per_warp);
    }
    {
        int threads = 512;
        int blocks = (n4 + threads - 1) / threads;
        fin_kernel<<<blocks, threads>>>((float4*)out, n4);
    }
}

// round 14
// speedup vs baseline: 1.2236x; 1.2236x over previous
#include <cuda_runtime.h>

#define NGMAX 4096
#define DCOLS 128
__device__ float g_Z[NGMAX];                 // zero-init at load; reset by fin_kernel
__device__ float g_S[NGMAX * DCOLS];         // zero-init at load; reset by fin_kernel

__device__ __forceinline__ float warp_bcast_sum(float p) {
    p += __shfl_xor_sync(0xFFFFFFFFu, p, 16);
    p += __shfl_xor_sync(0xFFFFFFFFu, p, 8);
    p += __shfl_xor_sync(0xFFFFFFFFu, p, 4);
    p += __shfl_xor_sync(0xFFFFFFFFu, p, 2);
    p += __shfl_xor_sync(0xFFFFFFFFu, p, 1);
    return p;
}

// One warp per chunk of rows_per_warp contiguous rows.
// Lane k holds columns [4k, 4k+4) as a float4. 4-row software pipeline
// (R3/R12-proven form, frozen). Accumulates into device scratch g_S / g_Z.
// R12 structure exactly; single delta: 32-bit (unsigned) index math, no
// occupancy cap (R13's forced cap caused spills).
__global__ void agg_kernel(const float* __restrict__ H,
                           const int*   __restrict__ batch,
                           const float* __restrict__ w,
                           const float* __restrict__ b,
                           int V, int rows_per_warp) {
    int warp = (blockIdx.x * blockDim.x + threadIdx.x) >> 5;
    int lane = threadIdx.x & 31;

    unsigned start = (unsigned)warp * (unsigned)rows_per_warp;
    if (start >= (unsigned)V) return;
    unsigned end = start + (unsigned)rows_per_warp;
    if (end > (unsigned)V) end = (unsigned)V;

    float4 w4 = reinterpret_cast<const float4*>(w)[lane];
    float bias = b[0];

    const float4* __restrict__ H4 = reinterpret_cast<const float4*>(H);

    float4 acc = make_float4(0.f, 0.f, 0.f, 0.f);
    float  zacc = 0.f;
    int    seg  = batch[start];

#define FLUSH()                                                         \
    do {                                                                \
        float* o = g_S + seg * DCOLS + lane * 4;                        \
        atomicAdd(o + 0, acc.x);                                        \
        atomicAdd(o + 1, acc.y);                                        \
        atomicAdd(o + 2, acc.z);                                        \
        atomicAdd(o + 3, acc.w);                                        \
        if (lane == 0) atomicAdd(&g_Z[seg], zacc);                      \
        acc = make_float4(0.f, 0.f, 0.f, 0.f);                          \
        zacc = 0.f;                                                     \
    } while (0)

#define ACCUM(s_, h_, l_)                                               \
    do {                                                                \
        if ((s_) != seg) { FLUSH(); seg = (s_); }                       \
        acc.x += (l_) * (h_).x;                                         \
        acc.y += (l_) * (h_).y;                                         \
        acc.z += (l_) * (h_).z;                                         \
        acc.w += (l_) * (h_).w;                                         \
        zacc  += (l_);                                                  \
    } while (0)

    unsigned r = start;
    for (; r + 4 <= end; r += 4) {
        // front-batched independent loads (MLP); streaming hint: H read once
        int4   bv = *reinterpret_cast<const int4*>(batch + r);
        float4 h0 = __ldcs(&H4[(r + 0) * (DCOLS / 4) + lane]);
        float4 h1 = __ldcs(&H4[(r + 1) * (DCOLS / 4) + lane]);
        float4 h2 = __ldcs(&H4[(r + 2) * (DCOLS / 4) + lane]);
        float4 h3 = __ldcs(&H4[(r + 3) * (DCOLS / 4) + lane]);

        float p0 = h0.x * w4.x + h0.y * w4.y + h0.z * w4.z + h0.w * w4.w;
        float p1 = h1.x * w4.x + h1.y * w4.y + h1.z * w4.z + h1.w * w4.w;
        float p2 = h2.x * w4.x + h2.y * w4.y + h2.z * w4.z + h2.w * w4.w;
        float p3 = h3.x * w4.x + h3.y * w4.y + h3.z * w4.z + h3.w * w4.w;

        // four independent butterfly chains — latencies overlap
        #pragma unroll
        for (int m = 16; m >= 1; m >>= 1) {
            p0 += __shfl_xor_sync(0xFFFFFFFFu, p0, m);
            p1 += __shfl_xor_sync(0xFFFFFFFFu, p1, m);
            p2 += __shfl_xor_sync(0xFFFFFFFFu, p2, m);
            p3 += __shfl_xor_sync(0xFFFFFFFFu, p3, m);
        }

        float l0 = __expf(p0 + bias);
        float l1 = __expf(p1 + bias);
        float l2 = __expf(p2 + bias);
        float l3 = __expf(p3 + bias);

        ACCUM(bv.x, h0, l0);
        ACCUM(bv.y, h1, l1);
        ACCUM(bv.z, h2, l2);
        ACCUM(bv.w, h3, l3);
    }

    // tail
    for (; r < end; ++r) {
        int s = batch[r];
        float4 h = __ldcs(&H4[r * (DCOLS / 4) + lane]);
        float p = h.x * w4.x + h.y * w4.y + h.z * w4.z + h.w * w4.w;
        p = warp_bcast_sum(p);
        float l = __expf(p + bias);
        ACCUM(s, h, l);
    }

    FLUSH();
#undef ACCUM
#undef FLUSH
}

// out[i] = S[i] / Z[i/128]; then reset scratch to zero for the next replay.
// All 32 threads of a warp read the same g_Z[g] (i>>5 constant per warp),
// so lane 0 can safely re-zero it after __syncwarp().
__global__ void fin_kernel(float4* __restrict__ out4, int n4) {
    int i = blockIdx.x * blockDim.x + threadIdx.x;
    if (i >= n4) return;
    int g = i >> 5;                 // (i*4)/128
    float z = g_Z[g];
    float4 v = reinterpret_cast<float4*>(g_S)[i];
    if (z > 0.f) {
        float inv = 1.0f / z;
        v.x *= inv; v.y *= inv; v.z *= inv; v.w *= inv;
    } else {
        v = make_float4(0.f, 0.f, 0.f, 0.f);
    }
    out4[i] = v;
    // reset scratch for next graph replay
    reinterpret_cast<float4*>(g_S)[i] = make_float4(0.f, 0.f, 0.f, 0.f);
    __syncwarp();
    if ((i & 31) == 0) g_Z[g] = 0.f;
}

extern "C" void kernel_launch(void* const* d_in, const int* in_sizes, int n_in,
                              void* d_out, int out_size) {
    const float* H     = (const float*)d_in[0];
    const int*   batch = (const int*)d_in[1];
    const float* w     = (const float*)d_in[2];
    const float* b     = (const float*)d_in[3];
    float*       out   = (float*)d_out;

    int V  = in_sizes[1];           // number of rows
    int n4 = out_size / 4;          // float4 count (= ng*32)

    {
        const int rows_per_warp = 64;
        long warps = ((long)V + rows_per_warp - 1) / rows_per_warp;
        int threads = 256;
        long blocks = (warps * 32 + threads - 1) / threads;
        agg_kernel<<<(int)blocks, threads>>>(H, batch, w, b, V, rows_per_warp);
    }
    {
        int threads = 512;
        int blocks = (n4 + threads - 1) / threads;
        fin_kernel<<<blocks, threads>>>((float4*)out, n4);
    }
}